// round 2
// baseline (speedup 1.0000x reference)
#include <cuda_runtime.h>

#define CH 32
#define SEGS 33
#define NMAX 50000
#define EMAX 200000

// ---- device-global scratch ----
__device__ float g_bp_e[32], g_bp_a[32];          // compacted breakpoints, sentinel 2.0
__device__ float g_trep_e[SEGS], g_trep_a[SEGS];  // per-segment representative t
__device__ int   g_nseg_e, g_nseg_a;              // effective segment counts
__device__ unsigned long long g_AB[SEGS * 1024];  // (s,i,lane) packed {A,B} float2
__device__ float g_aA[SEGS * 32], g_aB[SEGS * 32];
__device__ int   g_ecnt[SEGS];                    // per-segment edge count / cursor
__device__ int   g_ebuck[SEGS * EMAX];            // bucketed edge ids
__device__ float g_cnt[SEGS * NMAX], g_ts[SEGS * NMAX];  // angle (seg,node) accum

// ---------------------------------------------------------------------------
// K1: compact breakpoints to (0,1), sort, segment representatives. 1 block.
// ---------------------------------------------------------------------------
__global__ void k_pre1(const float* __restrict__ eW1, const float* __restrict__ eb1,
                       const float* __restrict__ aW1, const float* __restrict__ ab1) {
    int t = threadIdx.x;
    if (t < SEGS) g_ecnt[t] = 0;
    if (t == 0) {
        float tmp[32]; int c = 0;
        for (int i = 0; i < 32; i++) {
            float w = eW1[i], b = eb1[i];
            if (w != 0.0f) { float p = -b / w; if (p > 0.0f && p < 1.0f) tmp[c++] = p; }
        }
        for (int i = 1; i < c; i++) {
            float v = tmp[i]; int j = i - 1;
            while (j >= 0 && tmp[j] > v) { tmp[j + 1] = tmp[j]; j--; }
            tmp[j + 1] = v;
        }
        for (int i = 0; i < 32; i++) g_bp_e[i] = (i < c) ? tmp[i] : 2.0f;
        g_nseg_e = c + 1;
        for (int s = 0; s <= c; s++) {
            float lo = (s == 0) ? 0.0f : tmp[s - 1];
            float hi = (s == c) ? 1.0f : tmp[s];
            g_trep_e[s] = 0.5f * (lo + hi);
        }
    }
    if (t == 1) {
        float tmp[32]; int c = 0;
        for (int i = 0; i < 32; i++) {
            float w = aW1[i], b = ab1[i];
            if (w != 0.0f) { float p = -b / w; if (p > 0.0f && p < 1.0f) tmp[c++] = p; }
        }
        for (int i = 1; i < c; i++) {
            float v = tmp[i]; int j = i - 1;
            while (j >= 0 && tmp[j] > v) { tmp[j + 1] = tmp[j]; j--; }
            tmp[j + 1] = v;
        }
        for (int i = 0; i < 32; i++) g_bp_a[i] = (i < c) ? tmp[i] : 2.0f;
        g_nseg_a = c + 1;
        for (int s = 0; s <= c; s++) {
            float lo = (s == 0) ? 0.0f : tmp[s - 1];
            float hi = (s == c) ? 1.0f : tmp[s];
            g_trep_a[s] = 0.5f * (lo + hi);
        }
    }
}

// ---------------------------------------------------------------------------
// K2: table build (blocks 0..SEGS) + zero out/accumulators (remaining blocks)
// ---------------------------------------------------------------------------
__global__ void k_setup(const float* __restrict__ eW1, const float* __restrict__ eb1,
                        const float* __restrict__ eW2, const float* __restrict__ eb2,
                        const float* __restrict__ aW1, const float* __restrict__ ab1,
                        const float* __restrict__ aW2, const float* __restrict__ ab2,
                        float* __restrict__ out, int N) {
    int blk = blockIdx.x;
    if (blk < SEGS) {
        int s = blk;
        if (s >= g_nseg_e) return;
        __shared__ float w1[32], b1[32];
        if (threadIdx.x < 32) { w1[threadIdx.x] = eW1[threadIdx.x]; b1[threadIdx.x] = eb1[threadIdx.x]; }
        __syncthreads();
        float trep = g_trep_e[s];
        float* ABf = (float*)g_AB;
        for (int io = threadIdx.x; io < 1024; io += blockDim.x) {
            float a = eb2[io], b = 0.0f;
            #pragma unroll
            for (int k = 0; k < 32; k++) {
                if (w1[k] * trep + b1[k] > 0.0f) {
                    float w2 = eW2[k * 1024 + io];
                    a = fmaf(b1[k], w2, a);
                    b = fmaf(w1[k], w2, b);
                }
            }
            int i = io >> 5, o = io & 31;
            int base = (((s * 32 + i) * 32) + o) * 2;
            ABf[base + 0] = a;
            ABf[base + 1] = b;
        }
    } else if (blk == SEGS) {
        int ns = g_nseg_a;
        for (int idx = threadIdx.x; idx < ns * 32; idx += blockDim.x) {
            int s2 = idx >> 5, o = idx & 31;
            float trep = g_trep_a[s2];
            float a = ab2[o], b = 0.0f;
            #pragma unroll
            for (int k = 0; k < 32; k++) {
                float w = aW1[k], bb = ab1[k];
                if (w * trep + bb > 0.0f) {
                    float w2 = aW2[k * 32 + o];
                    a = fmaf(bb, w2, a);
                    b = fmaf(w, w2, b);
                }
            }
            g_aA[idx] = a;
            g_aB[idx] = b;
        }
    } else {
        long total_o = (long)N * 32;
        long total_c = (long)g_nseg_a * NMAX;
        long nb = (long)gridDim.x - SEGS - 1;
        long gid = (long)(blk - SEGS - 1) * blockDim.x + threadIdx.x;
        long stride = nb * blockDim.x;
        for (long i = gid; i < total_o; i += stride) out[i] = 0.0f;
        for (long i = gid; i < total_c; i += stride) { g_cnt[i] = 0.0f; g_ts[i] = 0.0f; }
    }
}

// ---------------------------------------------------------------------------
// K3: front pass — bucket edges by segment + angle (count, sum_t) scatter
// ---------------------------------------------------------------------------
__global__ void k_front(const int* __restrict__ ei, const float* __restrict__ ea,
                        const int* __restrict__ ai, const float* __restrict__ ang,
                        int E, int A) {
    __shared__ float sbe[32], sba[32];
    if (threadIdx.x < 32) { sbe[threadIdx.x] = g_bp_e[threadIdx.x]; sba[threadIdx.x] = g_bp_a[threadIdx.x]; }
    __syncthreads();
    int i = blockIdx.x * blockDim.x + threadIdx.x;
    if (i < E) {
        float t = __ldg(ea + i);
        int s = 0;
        #pragma unroll
        for (int k = 0; k < 32; k++) s += (sbe[k] <= t) ? 1 : 0;
        int pos = atomicAdd(&g_ecnt[s], 1);
        g_ebuck[s * EMAX + pos] = i;
    }
    if (i < A) {
        float t = __ldg(ang + i);
        int j = __ldg(ai + A + i);   // angle_index[1]
        int s = 0;
        #pragma unroll
        for (int k = 0; k < 32; k++) s += (sba[k] <= t) ? 1 : 0;
        atomicAdd(&g_cnt[s * NMAX + j], 1.0f);
        atomicAdd(&g_ts[s * NMAX + j], t);
    }
}

// ---------------------------------------------------------------------------
// K4: edge branch — warp per edge, A/B in registers (per segment), FFMA2
// ---------------------------------------------------------------------------
__global__ void k_edge(const float* __restrict__ x, const int* __restrict__ ei,
                       const float* __restrict__ ea, float* __restrict__ out, int E) {
    int s = blockIdx.y;
    if (s >= g_nseg_e) return;
    int cnt = g_ecnt[s];
    int wpc = gridDim.x * (blockDim.x >> 5);
    int w = blockIdx.x * (blockDim.x >> 5) + (threadIdx.x >> 5);
    if (w >= cnt) return;
    int lane = threadIdx.x & 31;

    // load packed {A,B} columns for this segment into registers
    unsigned long long ab[32];
    const unsigned long long* ABp = g_AB + s * 1024 + lane;
    #pragma unroll
    for (int i = 0; i < 32; i++) ab[i] = ABp[i * 32];

    const int* buck = g_ebuck + s * EMAX;
    for (int idx = w; idx < cnt; idx += wpc) {
        int e = buck[idx];
        float t = __ldg(ea + e);
        int row = __ldg(ei + e);
        int col = __ldg(ei + E + e);
        float u = __ldg(x + col * 32 + lane);
        unsigned long long acc2 = 0ull;   // packed (accA, accB) = (0.0f, 0.0f)
        #pragma unroll
        for (int i = 0; i < 32; i++) {
            float xi = __shfl_sync(0xffffffffu, u, i);
            unsigned long long xi2;
            asm("mov.b64 %0, {%1, %1};" : "=l"(xi2) : "f"(xi));
            asm("fma.rn.f32x2 %0, %1, %2, %0;" : "+l"(acc2) : "l"(xi2), "l"(ab[i]));
        }
        float accA, accB;
        asm("mov.b64 {%0, %1}, %2;" : "=f"(accA), "=f"(accB) : "l"(acc2));
        atomicAdd(out + row * 32 + lane, fmaf(t, accB, accA));
    }
}

// ---------------------------------------------------------------------------
// K5: angle branch pass 2 — dense per-node expansion. Warp per node.
// ---------------------------------------------------------------------------
__global__ void k_angle2(float* __restrict__ out, int N) {
    int j = (blockIdx.x * blockDim.x + threadIdx.x) >> 5;
    int lane = threadIdx.x & 31;
    if (j >= N) return;
    int ns = g_nseg_a;
    float acc = out[j * 32 + lane];
    for (int s = 0; s < ns; s++) {
        float c = g_cnt[s * NMAX + j];
        if (c != 0.0f) {
            float ts = g_ts[s * NMAX + j];
            acc = fmaf(c, g_aA[s * 32 + lane], acc);
            acc = fmaf(ts, g_aB[s * 32 + lane], acc);
        }
    }
    out[j * 32 + lane] = acc;
}

// ---------------------------------------------------------------------------
extern "C" void kernel_launch(void* const* d_in, const int* in_sizes, int n_in,
                              void* d_out, int out_size) {
    const float* x   = (const float*)d_in[0];
    const int*   ei  = (const int*)d_in[1];
    const float* ea  = (const float*)d_in[2];
    const int*   ai  = (const int*)d_in[3];
    const float* ang = (const float*)d_in[4];
    const float* eW1 = (const float*)d_in[5];
    const float* eb1 = (const float*)d_in[6];
    const float* eW2 = (const float*)d_in[7];
    const float* eb2 = (const float*)d_in[8];
    const float* aW1 = (const float*)d_in[9];
    const float* ab1 = (const float*)d_in[10];
    const float* aW2 = (const float*)d_in[11];
    const float* ab2 = (const float*)d_in[12];
    float* out = (float*)d_out;

    int N = in_sizes[0] / CH;
    int E = in_sizes[1] / 2;
    int A = in_sizes[3] / 3;

    k_pre1<<<1, 64>>>(eW1, eb1, aW1, ab1);
    k_setup<<<SEGS + 1 + 4096, 256>>>(eW1, eb1, eW2, eb2, aW1, ab1, aW2, ab2, out, N);
    int fb = ((E > A ? E : A) + 255) / 256;
    k_front<<<fb, 256>>>(ei, ea, ai, ang, E, A);
    dim3 ge(256, SEGS);
    k_edge<<<ge, 256>>>(x, ei, ea, out, E);
    k_angle2<<<(N * 32 + 255) / 256, 256>>>(out, N);
}

// round 3
// speedup vs baseline: 1.2180x; 1.2180x over previous
#include <cuda_runtime.h>

#define CH 32
#define SEGS 33
#define NMAX 50000
#define EMAX 200000
#define FULL 0xffffffffu

// ---- device-global scratch ----
__device__ float g_bp_e[32], g_bp_a[32];          // compacted breakpoints, sentinel 2.0
__device__ float g_trep_e[SEGS], g_trep_a[SEGS];  // per-segment representative t
__device__ int   g_nseg_e, g_nseg_a;              // effective segment counts
__device__ unsigned long long g_AB[SEGS * 1024];  // (s,i,lane) packed {A,B} float2
__device__ float g_aA[SEGS * 32], g_aB[SEGS * 32];
__device__ int   g_ecnt[SEGS];                    // per-segment edge count / cursor
__device__ int   g_ebuck[SEGS * EMAX];            // bucketed edge ids
__device__ __align__(16) float g_cnt[SEGS * NMAX];
__device__ __align__(16) float g_ts[SEGS * NMAX];

// ---------------------------------------------------------------------------
// K1: compact breakpoints to (0,1) via parallel rank sort. Warp0=edge, warp1=angle.
// ---------------------------------------------------------------------------
__global__ void k_pre(const float* __restrict__ eW1, const float* __restrict__ eb1,
                      const float* __restrict__ aW1, const float* __restrict__ ab1) {
    __shared__ float sorted[2][33];
    int warp = threadIdx.x >> 5, lane = threadIdx.x & 31;
    if (threadIdx.x < SEGS) g_ecnt[threadIdx.x] = 0;
    if (warp > 1) return;

    const float* W = (warp == 0) ? eW1 : aW1;
    const float* B = (warp == 0) ? eb1 : ab1;
    float w = W[lane], b = B[lane];
    float p = (w != 0.0f) ? (-b / w) : -1.0f;
    bool valid = (p > 0.0f && p < 1.0f);
    unsigned vm = __ballot_sync(FULL, valid);
    int c = __popc(vm);

    int rank = 0;
    #pragma unroll
    for (int i = 0; i < 32; i++) {
        float pi = __shfl_sync(FULL, p, i);
        bool vi = (vm >> i) & 1;
        if (vi && (pi < p || (pi == p && i < lane))) rank++;
    }
    if (valid) sorted[warp][rank] = p;
    __syncwarp();

    float bpv = (lane < c) ? sorted[warp][lane] : 2.0f;
    if (warp == 0) g_bp_e[lane] = bpv; else g_bp_a[lane] = bpv;
    if (lane == 0) { if (warp == 0) g_nseg_e = c + 1; else g_nseg_a = c + 1; }

    for (int s = lane; s <= c; s += 32) {
        float lo = (s == 0) ? 0.0f : sorted[warp][s - 1];
        float hi = (s == c) ? 1.0f : sorted[warp][s];
        float tr = 0.5f * (lo + hi);
        if (warp == 0) g_trep_e[s] = tr; else g_trep_a[s] = tr;
    }
}

// ---------------------------------------------------------------------------
// K2: table build (blocks 0..SEGS) + vectorized zeroing (remaining blocks)
// ---------------------------------------------------------------------------
__global__ void k_setup(const float* __restrict__ eW1, const float* __restrict__ eb1,
                        const float* __restrict__ eW2, const float* __restrict__ eb2,
                        const float* __restrict__ aW1, const float* __restrict__ ab1,
                        const float* __restrict__ aW2, const float* __restrict__ ab2,
                        float* __restrict__ out, int N) {
    int blk = blockIdx.x;
    if (blk < SEGS) {
        int s = blk;
        if (s >= g_nseg_e) return;
        __shared__ float w1[32], b1[32];
        if (threadIdx.x < 32) { w1[threadIdx.x] = eW1[threadIdx.x]; b1[threadIdx.x] = eb1[threadIdx.x]; }
        __syncthreads();
        float trep = g_trep_e[s];
        float* ABf = (float*)g_AB;
        for (int io = threadIdx.x; io < 1024; io += blockDim.x) {
            float a = eb2[io], b = 0.0f;
            #pragma unroll
            for (int k = 0; k < 32; k++) {
                if (w1[k] * trep + b1[k] > 0.0f) {
                    float w2 = eW2[k * 1024 + io];
                    a = fmaf(b1[k], w2, a);
                    b = fmaf(w1[k], w2, b);
                }
            }
            int i = io >> 5, o = io & 31;
            int base = (((s * 32 + i) * 32) + o) * 2;
            ABf[base + 0] = a;
            ABf[base + 1] = b;
        }
    } else if (blk == SEGS) {
        int ns = g_nseg_a;
        for (int idx = threadIdx.x; idx < ns * 32; idx += blockDim.x) {
            int s2 = idx >> 5, o = idx & 31;
            float trep = g_trep_a[s2];
            float a = ab2[o], b = 0.0f;
            #pragma unroll
            for (int k = 0; k < 32; k++) {
                float w = aW1[k], bb = ab1[k];
                if (w * trep + bb > 0.0f) {
                    float w2 = aW2[k * 32 + o];
                    a = fmaf(bb, w2, a);
                    b = fmaf(w, w2, b);
                }
            }
            g_aA[idx] = a;
            g_aB[idx] = b;
        }
    } else {
        // vectorized zeroing: out (N*32 floats) + g_cnt/g_ts (nseg_a*NMAX floats each)
        float4 z = make_float4(0.f, 0.f, 0.f, 0.f);
        long no = (long)N * 8;                       // float4 count for out
        long nc = (long)g_nseg_a * (NMAX / 4);       // float4 count for cnt/ts each
        long nb = (long)gridDim.x - SEGS - 1;
        long gid = (long)(blk - SEGS - 1) * blockDim.x + threadIdx.x;
        long stride = nb * blockDim.x;
        float4* o4 = (float4*)out;
        float4* c4 = (float4*)g_cnt;
        float4* t4 = (float4*)g_ts;
        for (long i = gid; i < no; i += stride) o4[i] = z;
        for (long i = gid; i < nc; i += stride) { c4[i] = z; t4[i] = z; }
    }
}

// ---------------------------------------------------------------------------
// K3: front pass — warp-aggregated edge bucketing + angle (count, sum_t) scatter
// ---------------------------------------------------------------------------
__global__ void k_front(const int* __restrict__ ei, const float* __restrict__ ea,
                        const int* __restrict__ ai, const float* __restrict__ ang,
                        int E, int A) {
    __shared__ float sbe[32], sba[32];
    if (threadIdx.x < 32) { sbe[threadIdx.x] = g_bp_e[threadIdx.x]; sba[threadIdx.x] = g_bp_a[threadIdx.x]; }
    __syncthreads();
    int i = blockIdx.x * blockDim.x + threadIdx.x;
    int lane = threadIdx.x & 31;

    // ---- edge bucketing (warp-aggregated cursor atomics) ----
    bool valid = (i < E);
    float t = valid ? __ldg(ea + i) : 0.0f;
    int seg = 0;
    #pragma unroll
    for (int k = 0; k < 32; k++) seg += (sbe[k] <= t) ? 1 : 0;
    int ns = g_nseg_e;
    for (int s = 0; s < ns; s++) {
        unsigned mask = __ballot_sync(FULL, valid && (seg == s));
        if (mask) {
            int leader = __ffs(mask) - 1;
            int base = 0;
            if (lane == leader) base = atomicAdd(&g_ecnt[s], __popc(mask));
            base = __shfl_sync(FULL, base, leader);
            if (valid && seg == s) {
                int pos = base + __popc(mask & ((1u << lane) - 1u));
                g_ebuck[s * EMAX + pos] = i;
            }
        }
    }

    // ---- angle scatter ----
    if (i < A) {
        float ta = __ldg(ang + i);
        int j = __ldg(ai + A + i);   // angle_index[1] = center node
        int sa = 0;
        #pragma unroll
        for (int k = 0; k < 32; k++) sa += (sba[k] <= ta) ? 1 : 0;
        atomicAdd(&g_cnt[sa * NMAX + j], 1.0f);
        atomicAdd(&g_ts[sa * NMAX + j], ta);
    }
}

// ---------------------------------------------------------------------------
// K4: edge branch (y slices 0..SEGS-1): warp per 4 edges, register A/B, FFMA2.
//     Last y slice: angle expansion (atomicAdd, race-free vs edge atomics).
// ---------------------------------------------------------------------------
__global__ void __launch_bounds__(256, 2)
k_edge(const float* __restrict__ x, const int* __restrict__ ei,
       const float* __restrict__ ea, float* __restrict__ out, int E, int N) {
    int lane = threadIdx.x & 31;
    int w = blockIdx.x * (blockDim.x >> 5) + (threadIdx.x >> 5);
    int wpc = gridDim.x * (blockDim.x >> 5);

    if (blockIdx.y == SEGS) {
        // ---- angle expansion: out[j,:] += cnt*aA[s] + ts*aB[s] ----
        int ns = g_nseg_a;
        for (int j = w; j < N; j += wpc) {
            float acc = 0.0f;
            for (int s = 0; s < ns; s++) {
                float c = g_cnt[s * NMAX + j];
                if (c != 0.0f) {
                    float ts = g_ts[s * NMAX + j];
                    acc = fmaf(c, g_aA[s * 32 + lane], acc);
                    acc = fmaf(ts, g_aB[s * 32 + lane], acc);
                }
            }
            if (acc != 0.0f) atomicAdd(out + j * 32 + lane, acc);
        }
        return;
    }

    int s = blockIdx.y;
    if (s >= g_nseg_e) return;
    int cnt = g_ecnt[s];
    if (w * 4 >= cnt) return;

    // per-segment packed {A,B} table into registers (64 regs)
    unsigned long long ab[32];
    const unsigned long long* ABp = g_AB + s * 1024 + lane;
    #pragma unroll
    for (int i = 0; i < 32; i++) ab[i] = ABp[i * 32];

    const int* buck = g_ebuck + s * EMAX;
    int stride = wpc * 4;
    for (int idx = w * 4; idx < cnt; idx += stride) {
        int rem = cnt - idx;                 // warp-uniform
        if (rem >= 4) {
            int e0 = __ldg(buck + idx + 0), e1 = __ldg(buck + idx + 1);
            int e2 = __ldg(buck + idx + 2), e3 = __ldg(buck + idx + 3);
            float t0 = __ldg(ea + e0), t1 = __ldg(ea + e1), t2 = __ldg(ea + e2), t3 = __ldg(ea + e3);
            int r0 = __ldg(ei + e0), r1 = __ldg(ei + e1), r2 = __ldg(ei + e2), r3 = __ldg(ei + e3);
            float u0 = __ldg(x + __ldg(ei + E + e0) * 32 + lane);
            float u1 = __ldg(x + __ldg(ei + E + e1) * 32 + lane);
            float u2 = __ldg(x + __ldg(ei + E + e2) * 32 + lane);
            float u3 = __ldg(x + __ldg(ei + E + e3) * 32 + lane);
            unsigned long long a0 = 0ull, a1 = 0ull, a2 = 0ull, a3 = 0ull;
            #pragma unroll
            for (int i = 0; i < 32; i++) {
                unsigned long long m = ab[i];
                float x0 = __shfl_sync(FULL, u0, i);
                float x1 = __shfl_sync(FULL, u1, i);
                float x2 = __shfl_sync(FULL, u2, i);
                float x3 = __shfl_sync(FULL, u3, i);
                unsigned long long p0, p1, p2, p3;
                asm("mov.b64 %0, {%1, %1};" : "=l"(p0) : "f"(x0));
                asm("mov.b64 %0, {%1, %1};" : "=l"(p1) : "f"(x1));
                asm("mov.b64 %0, {%1, %1};" : "=l"(p2) : "f"(x2));
                asm("mov.b64 %0, {%1, %1};" : "=l"(p3) : "f"(x3));
                asm("fma.rn.f32x2 %0, %1, %2, %0;" : "+l"(a0) : "l"(p0), "l"(m));
                asm("fma.rn.f32x2 %0, %1, %2, %0;" : "+l"(a1) : "l"(p1), "l"(m));
                asm("fma.rn.f32x2 %0, %1, %2, %0;" : "+l"(a2) : "l"(p2), "l"(m));
                asm("fma.rn.f32x2 %0, %1, %2, %0;" : "+l"(a3) : "l"(p3), "l"(m));
            }
            float cA, cB;
            asm("mov.b64 {%0, %1}, %2;" : "=f"(cA), "=f"(cB) : "l"(a0));
            atomicAdd(out + r0 * 32 + lane, fmaf(t0, cB, cA));
            asm("mov.b64 {%0, %1}, %2;" : "=f"(cA), "=f"(cB) : "l"(a1));
            atomicAdd(out + r1 * 32 + lane, fmaf(t1, cB, cA));
            asm("mov.b64 {%0, %1}, %2;" : "=f"(cA), "=f"(cB) : "l"(a2));
            atomicAdd(out + r2 * 32 + lane, fmaf(t2, cB, cA));
            asm("mov.b64 {%0, %1}, %2;" : "=f"(cA), "=f"(cB) : "l"(a3));
            atomicAdd(out + r3 * 32 + lane, fmaf(t3, cB, cA));
        } else {
            for (int k = 0; k < rem; k++) {
                int e = __ldg(buck + idx + k);
                float t = __ldg(ea + e);
                int row = __ldg(ei + e);
                float u = __ldg(x + __ldg(ei + E + e) * 32 + lane);
                unsigned long long a0 = 0ull;
                #pragma unroll
                for (int i = 0; i < 32; i++) {
                    float xi = __shfl_sync(FULL, u, i);
                    unsigned long long p;
                    asm("mov.b64 %0, {%1, %1};" : "=l"(p) : "f"(xi));
                    asm("fma.rn.f32x2 %0, %1, %2, %0;" : "+l"(a0) : "l"(p), "l"(ab[i]));
                }
                float cA, cB;
                asm("mov.b64 {%0, %1}, %2;" : "=f"(cA), "=f"(cB) : "l"(a0));
                atomicAdd(out + row * 32 + lane, fmaf(t, cB, cA));
            }
        }
    }
}

// ---------------------------------------------------------------------------
extern "C" void kernel_launch(void* const* d_in, const int* in_sizes, int n_in,
                              void* d_out, int out_size) {
    const float* x   = (const float*)d_in[0];
    const int*   ei  = (const int*)d_in[1];
    const float* ea  = (const float*)d_in[2];
    const int*   ai  = (const int*)d_in[3];
    const float* ang = (const float*)d_in[4];
    const float* eW1 = (const float*)d_in[5];
    const float* eb1 = (const float*)d_in[6];
    const float* eW2 = (const float*)d_in[7];
    const float* eb2 = (const float*)d_in[8];
    const float* aW1 = (const float*)d_in[9];
    const float* ab1 = (const float*)d_in[10];
    const float* aW2 = (const float*)d_in[11];
    const float* ab2 = (const float*)d_in[12];
    float* out = (float*)d_out;

    int N = in_sizes[0] / CH;
    int E = in_sizes[1] / 2;
    int A = in_sizes[3] / 3;

    k_pre<<<1, 64>>>(eW1, eb1, aW1, ab1);
    k_setup<<<SEGS + 1 + 512, 256>>>(eW1, eb1, eW2, eb2, aW1, ab1, aW2, ab2, out, N);
    int fb = ((E > A ? E : A) + 255) / 256;
    k_front<<<fb, 256>>>(ei, ea, ai, ang, E, A);
    dim3 ge(256, SEGS + 1);
    k_edge<<<ge, 256>>>(x, ei, ea, out, E, N);
}